// round 1
// baseline (speedup 1.0000x reference)
#include <cuda_runtime.h>
#include <math.h>
#include <float.h>

#define T_SEQ  4096
#define NDIM   2048
#define NHEADS 16
#define NKV    4
#define HD     128
#define KVDIM  512

// Scratch (device globals — no runtime allocation allowed)
__device__ float g_q[(size_t)T_SEQ * NDIM];
__device__ float g_k[(size_t)T_SEQ * KVDIM];
__device__ float g_v[(size_t)T_SEQ * KVDIM];
__device__ float g_att[(size_t)T_SEQ * NDIM];

// ---------------------------------------------------------------------------
// GEMM (TN): C[M,N] = A[M,K] * B[N,K]^T ; A,B row-major with K contiguous.
// Tiles: BM=128, BN=64, BK=32; 256 threads; per-thread 8x4 microtile.
// ---------------------------------------------------------------------------
__global__ void __launch_bounds__(256)
gemm_tn(const float* __restrict__ A, const float* __restrict__ B,
        float* __restrict__ C, int M, int N, int K)
{
    constexpr int BM = 128, BN = 64, BK = 32;
    __shared__ float As[BK][BM + 4];
    __shared__ float Bs[BK][BN + 4];

    const int tid = threadIdx.x;
    const int tx  = tid & 15;   // N dir (16)
    const int ty  = tid >> 4;   // M dir (16)
    const int m0  = blockIdx.y * BM;
    const int n0  = blockIdx.x * BN;

    float acc[8][4];
#pragma unroll
    for (int i = 0; i < 8; ++i)
#pragma unroll
        for (int j = 0; j < 4; ++j) acc[i][j] = 0.f;

    const int kq = tid & 7;     // float4 index within BK=32 (8 per row)
    const int mr = tid >> 3;    // 0..31

    for (int k0 = 0; k0 < K; k0 += BK) {
#pragma unroll
        for (int r = 0; r < 4; ++r) {
            int m = mr + 32 * r;
            float4 va = *(const float4*)(A + (size_t)(m0 + m) * K + k0 + kq * 4);
            As[kq * 4 + 0][m] = va.x; As[kq * 4 + 1][m] = va.y;
            As[kq * 4 + 2][m] = va.z; As[kq * 4 + 3][m] = va.w;
        }
#pragma unroll
        for (int r = 0; r < 2; ++r) {
            int n = mr + 32 * r;
            float4 vb = *(const float4*)(B + (size_t)(n0 + n) * K + k0 + kq * 4);
            Bs[kq * 4 + 0][n] = vb.x; Bs[kq * 4 + 1][n] = vb.y;
            Bs[kq * 4 + 2][n] = vb.z; Bs[kq * 4 + 3][n] = vb.w;
        }
        __syncthreads();

#pragma unroll 8
        for (int kk = 0; kk < BK; ++kk) {
            float4 a0 = *(const float4*)(&As[kk][ty * 8]);
            float4 a1 = *(const float4*)(&As[kk][ty * 8 + 4]);
            float4 b  = *(const float4*)(&Bs[kk][tx * 4]);
            float a[8] = {a0.x, a0.y, a0.z, a0.w, a1.x, a1.y, a1.z, a1.w};
            float bv[4] = {b.x, b.y, b.z, b.w};
#pragma unroll
            for (int i = 0; i < 8; ++i)
#pragma unroll
                for (int j = 0; j < 4; ++j)
                    acc[i][j] = fmaf(a[i], bv[j], acc[i][j]);
        }
        __syncthreads();
    }

#pragma unroll
    for (int i = 0; i < 8; ++i) {
        float4 v = make_float4(acc[i][0], acc[i][1], acc[i][2], acc[i][3]);
        *(float4*)(C + (size_t)(m0 + ty * 8 + i) * N + n0 + tx * 4) = v;
    }
}

// ---------------------------------------------------------------------------
// Per-head RMSNorm + RoPE (+ optional gain). One block per (token, head),
// 128 threads (one per head dim). In-place.
// ---------------------------------------------------------------------------
__global__ void qk_prep(float* __restrict__ p, const float* __restrict__ gain,
                        int stride)
{
    const int t = blockIdx.x;
    const int h = blockIdx.y;
    const int d = threadIdx.x;          // 0..127
    float* row = p + (size_t)t * stride + h * HD;

    __shared__ float sx[HD];
    __shared__ float wsum[4];

    float v = row[d];
    sx[d] = v;
    float ss = v * v;
#pragma unroll
    for (int o = 16; o; o >>= 1) ss += __shfl_xor_sync(0xffffffffu, ss, o);
    if ((d & 31) == 0) wsum[d >> 5] = ss;
    __syncthreads();
    float tot = wsum[0] + wsum[1] + wsum[2] + wsum[3];
    float rn = rsqrtf(tot * (1.0f / HD) + 1.1920928955078125e-07f);

    const int j = d & 63;
    // inv_freq = 10000^(-(2j)/128); compute in double for correct rounding
    float inv_freq = (float)exp(-(double)(2 * j) * (1.0 / 128.0) * 9.210340371976184);
    float ang = (float)t * inv_freq;
    float sn, cs;
    sincosf(ang, &sn, &cs);

    float x1 = sx[j];
    float x2 = sx[j + 64];
    float val = (d < 64) ? (x1 * cs + x2 * sn) : (x2 * cs - x1 * sn);
    val *= rn;
    if (gain) val *= gain[h];
    row[d] = val;
}

// ---------------------------------------------------------------------------
// Flash-style causal attention (fp32). One block = 64 query rows x 1 head.
// 256 threads (8 warps); warp owns 8 query rows.
// S-phase: 4 lanes/row, each lane 16 key cols (c = j*4 + grp).
// PV-phase: lane owns head-dim float4 (d = l*4), all 8 rows of its warp.
// ---------------------------------------------------------------------------
__global__ void __launch_bounds__(256)
attn_kernel(const float* __restrict__ Q, const float* __restrict__ K,
            const float* __restrict__ V, float* __restrict__ O)
{
    extern __shared__ float smem[];
    float* Qs    = smem;                  // 64 x 132
    float* Ks    = Qs + 64 * 132;         // 64 x 132
    float* Vs    = Ks + 64 * 132;         // 64 x 128
    float* Ps    = Vs + 64 * 128;         // 64 x 68
    float* rowst = Ps + 64 * 68;          // 64

    const int qt  = blockIdx.x;           // 0..63
    const int h   = blockIdx.y;           // 0..15
    const int q0  = qt * 64;
    const int kvh = h >> 2;               // rep = 4
    const int tid = threadIdx.x;
    const int w   = tid >> 5;
    const int l   = tid & 31;
    const int rloc = w * 8 + (l >> 2);
    const int grp  = l & 3;
    const int qg   = q0 + rloc;

    // Load Q tile
    for (int i = tid; i < 64 * 32; i += 256) {
        int r = i >> 5, c = i & 31;
        *(float4*)(Qs + r * 132 + c * 4) =
            *(const float4*)(Q + (size_t)(q0 + r) * NDIM + h * HD + c * 4);
    }

    float m_i = -FLT_MAX, l_i = 0.f;
    float o[8][4];
#pragma unroll
    for (int r = 0; r < 8; ++r)
#pragma unroll
        for (int e = 0; e < 4; ++e) o[r][e] = 0.f;

    const float scale = 0.08838834764831845f;   // 1/sqrt(128)

    for (int k0 = 0; k0 <= q0; k0 += 64) {
        __syncthreads();   // prior tile's smem consumers done
        for (int i = tid; i < 64 * 32; i += 256) {
            int r = i >> 5, c = i & 31;
            *(float4*)(Ks + r * 132 + c * 4) =
                *(const float4*)(K + (size_t)(k0 + r) * KVDIM + kvh * HD + c * 4);
            *(float4*)(Vs + r * 128 + c * 4) =
                *(const float4*)(V + (size_t)(k0 + r) * KVDIM + kvh * HD + c * 4);
        }
        __syncthreads();

        // ---- S = Q K^T for this tile ----
        float s[16];
#pragma unroll
        for (int j = 0; j < 16; ++j) s[j] = 0.f;

        const float* qrow = Qs + rloc * 132;
#pragma unroll 4
        for (int d4 = 0; d4 < 32; ++d4) {
            float4 qv = *(const float4*)(qrow + d4 * 4);
#pragma unroll
            for (int j = 0; j < 16; ++j) {
                float4 kv = *(const float4*)(Ks + (j * 4 + grp) * 132 + d4 * 4);
                s[j] = fmaf(qv.x, kv.x, s[j]);
                s[j] = fmaf(qv.y, kv.y, s[j]);
                s[j] = fmaf(qv.z, kv.z, s[j]);
                s[j] = fmaf(qv.w, kv.w, s[j]);
            }
        }

        // ---- scale + causal mask + online softmax stats ----
        float mt = -FLT_MAX;
#pragma unroll
        for (int j = 0; j < 16; ++j) {
            s[j] *= scale;
            if (k0 + j * 4 + grp > qg) s[j] = -FLT_MAX;
            mt = fmaxf(mt, s[j]);
        }
        mt = fmaxf(mt, __shfl_xor_sync(0xffffffffu, mt, 1));
        mt = fmaxf(mt, __shfl_xor_sync(0xffffffffu, mt, 2));
        float m_new = fmaxf(m_i, mt);
        float alpha = expf(m_i - m_new);

        float rowsum = 0.f;
#pragma unroll
        for (int j = 0; j < 16; ++j) {
            float pj = expf(s[j] - m_new);
            Ps[rloc * 68 + j * 4 + grp] = pj;
            rowsum += pj;
        }
        rowsum += __shfl_xor_sync(0xffffffffu, rowsum, 1);
        rowsum += __shfl_xor_sync(0xffffffffu, rowsum, 2);
        l_i = l_i * alpha + rowsum;
        m_i = m_new;
        if (grp == 0) rowst[rloc] = alpha;
        __syncwarp();

        // ---- O = O*alpha + P V ----
#pragma unroll
        for (int r = 0; r < 8; ++r) {
            float a = rowst[w * 8 + r];
#pragma unroll
            for (int e = 0; e < 4; ++e) o[r][e] *= a;
        }
#pragma unroll 2
        for (int c4 = 0; c4 < 16; ++c4) {
            float4 v0 = *(const float4*)(Vs + (c4 * 4 + 0) * 128 + l * 4);
            float4 v1 = *(const float4*)(Vs + (c4 * 4 + 1) * 128 + l * 4);
            float4 v2 = *(const float4*)(Vs + (c4 * 4 + 2) * 128 + l * 4);
            float4 v3 = *(const float4*)(Vs + (c4 * 4 + 3) * 128 + l * 4);
#pragma unroll
            for (int r = 0; r < 8; ++r) {
                float4 pp = *(const float4*)(Ps + (w * 8 + r) * 68 + c4 * 4);
                o[r][0] = fmaf(pp.x, v0.x, o[r][0]); o[r][0] = fmaf(pp.y, v1.x, o[r][0]);
                o[r][0] = fmaf(pp.z, v2.x, o[r][0]); o[r][0] = fmaf(pp.w, v3.x, o[r][0]);
                o[r][1] = fmaf(pp.x, v0.y, o[r][1]); o[r][1] = fmaf(pp.y, v1.y, o[r][1]);
                o[r][1] = fmaf(pp.z, v2.y, o[r][1]); o[r][1] = fmaf(pp.w, v3.y, o[r][1]);
                o[r][2] = fmaf(pp.x, v0.z, o[r][2]); o[r][2] = fmaf(pp.y, v1.z, o[r][2]);
                o[r][2] = fmaf(pp.z, v2.z, o[r][2]); o[r][2] = fmaf(pp.w, v3.z, o[r][2]);
                o[r][3] = fmaf(pp.x, v0.w, o[r][3]); o[r][3] = fmaf(pp.y, v1.w, o[r][3]);
                o[r][3] = fmaf(pp.z, v2.w, o[r][3]); o[r][3] = fmaf(pp.w, v3.w, o[r][3]);
            }
        }
    }

    __syncwarp();                      // PV readers done before rowst reuse
    if (grp == 0) rowst[rloc] = 1.0f / l_i;
    __syncwarp();

#pragma unroll
    for (int r = 0; r < 8; ++r) {
        float inv = rowst[w * 8 + r];
        float4 v = make_float4(o[r][0] * inv, o[r][1] * inv,
                               o[r][2] * inv, o[r][3] * inv);
        *(float4*)(O + (size_t)(q0 + w * 8 + r) * NDIM + h * HD + l * 4) = v;
    }
}

// ---------------------------------------------------------------------------
extern "C" void kernel_launch(void* const* d_in, const int* in_sizes, int n_in,
                              void* d_out, int out_size)
{
    const float* x  = (const float*)d_in[0];
    const float* Wq = (const float*)d_in[1];
    const float* Wk = (const float*)d_in[2];
    const float* Wv = (const float*)d_in[3];
    const float* Wo = (const float*)d_in[4];
    const float* qg = (const float*)d_in[5];
    float* out = (float*)d_out;

    float *q, *k, *v, *att;
    cudaGetSymbolAddress((void**)&q,   g_q);
    cudaGetSymbolAddress((void**)&k,   g_k);
    cudaGetSymbolAddress((void**)&v,   g_v);
    cudaGetSymbolAddress((void**)&att, g_att);

    // Projections: q = x Wq^T, k = x Wk^T, v = x Wv^T
    gemm_tn<<<dim3(NDIM  / 64, T_SEQ / 128), 256>>>(x, Wq, q, T_SEQ, NDIM,  NDIM);
    gemm_tn<<<dim3(KVDIM / 64, T_SEQ / 128), 256>>>(x, Wk, k, T_SEQ, KVDIM, NDIM);
    gemm_tn<<<dim3(KVDIM / 64, T_SEQ / 128), 256>>>(x, Wv, v, T_SEQ, KVDIM, NDIM);

    // RMSNorm + RoPE (+gain for q)
    qk_prep<<<dim3(T_SEQ, NHEADS), 128>>>(q, qg, NDIM);
    qk_prep<<<dim3(T_SEQ, NKV),    128>>>(k, nullptr, KVDIM);

    // Flash attention
    const int smem_bytes = (64 * 132 * 2 + 64 * 128 + 64 * 68 + 64) * 4;
    cudaFuncSetAttribute(attn_kernel,
                         cudaFuncAttributeMaxDynamicSharedMemorySize, smem_bytes);
    attn_kernel<<<dim3(T_SEQ / 64, NHEADS), 256, smem_bytes>>>(q, k, v, att);

    // Output projection
    gemm_tn<<<dim3(NDIM / 64, T_SEQ / 128), 256>>>(att, Wo, out, T_SEQ, NDIM, NDIM);
}

// round 3
// speedup vs baseline: 1.4397x; 1.4397x over previous
#include <cuda_runtime.h>
#include <math.h>
#include <float.h>
#include <stdint.h>

#define T_SEQ  4096
#define NDIM   2048
#define NHEADS 16
#define NKV    4
#define HD     128
#define KVDIM  512

// Scratch (device globals — no runtime allocation allowed)
__device__ float g_q[(size_t)T_SEQ * NDIM];
__device__ float g_k[(size_t)T_SEQ * KVDIM];
__device__ float g_v[(size_t)T_SEQ * KVDIM];
__device__ float g_att[(size_t)T_SEQ * NDIM];
__device__ float g_invf[64];
__device__ float g_cos[(size_t)T_SEQ * 64];
__device__ float g_sin[(size_t)T_SEQ * 64];

// ---------------------------------------------------------------------------
// Helpers
// ---------------------------------------------------------------------------
__device__ __forceinline__ uint32_t smem_u32(const void* p) {
    uint32_t a;
    asm("{ .reg .u64 t; cvta.to.shared.u64 t, %1; cvt.u32.u64 %0, t; }"
        : "=r"(a) : "l"(p));
    return a;
}
__device__ __forceinline__ uint32_t f2tf32(float f) {
    uint32_t r;
    asm("cvt.rna.tf32.f32 %0, %1;" : "=r"(r) : "f"(f));
    return r;
}
__device__ __forceinline__ void cpa16(uint32_t dst, const void* src) {
    asm volatile("cp.async.cg.shared.global [%0], [%1], 16;" :: "r"(dst), "l"(src));
}
__device__ __forceinline__ void mma_tf32(float* c, const uint32_t* a, const uint32_t* b) {
    asm volatile(
        "mma.sync.aligned.m16n8k8.row.col.f32.tf32.tf32.f32 "
        "{%0,%1,%2,%3}, {%4,%5,%6,%7}, {%8,%9}, {%0,%1,%2,%3};"
        : "+f"(c[0]), "+f"(c[1]), "+f"(c[2]), "+f"(c[3])
        : "r"(a[0]), "r"(a[1]), "r"(a[2]), "r"(a[3]), "r"(b[0]), "r"(b[1]));
}

// ---------------------------------------------------------------------------
// mma.sync tf32 GEMM (TN): C[M,N] = A[M,K] * B[N,K]^T, fp32 in/out.
// CTA tile 128x128, BK=32, 256 threads, warp tile 64x32 (2M x 4N warps).
// cp.async double-buffered smem; stride-36 rows (conflict-free frag loads).
// ---------------------------------------------------------------------------
#define GS 36                      // smem row stride (floats)
#define TILE_F (128 * GS)          // floats per A- or B-tile

__global__ void __launch_bounds__(256)
gemm_mma(const float* __restrict__ A, const float* __restrict__ B,
         float* __restrict__ C, int M, int N, int K)
{
    extern __shared__ float sm[];
    // buffer b: As at sm + b*2*TILE_F, Bs at sm + b*2*TILE_F + TILE_F
    const int tid  = threadIdx.x;
    const int wid  = tid >> 5;
    const int lane = tid & 31;
    const int wm   = (wid >> 2) * 64;       // warp M offset: 0 / 64
    const int wn   = (wid & 3) * 32;        // warp N offset: 0..96
    const int m0   = blockIdx.y * 128;
    const int n0   = blockIdx.x * 128;
    const int lr   = lane >> 2;             // 0..7
    const int lc   = lane & 3;              // 0..3

    float acc[4][4][4];
#pragma unroll
    for (int i = 0; i < 4; ++i)
#pragma unroll
        for (int j = 0; j < 4; ++j)
#pragma unroll
            for (int e = 0; e < 4; ++e) acc[i][j][e] = 0.f;

    const uint32_t sb = smem_u32(sm);

    auto load_chunk = [&](int c, int b) {
        const float* Ab = A + (size_t)m0 * K + c * 32;
        const float* Bb = B + (size_t)n0 * K + c * 32;
        const uint32_t abase = sb + (uint32_t)(b * 2 * TILE_F) * 4u;
        const uint32_t bbase = abase + (uint32_t)TILE_F * 4u;
#pragma unroll
        for (int i = 0; i < 4; ++i) {
            int lin = i * 256 + tid;           // 0..1023
            int row = lin >> 3, c4 = lin & 7;
            cpa16(abase + (uint32_t)(row * GS + c4 * 4) * 4u,
                  Ab + (size_t)row * K + c4 * 4);
        }
#pragma unroll
        for (int i = 0; i < 4; ++i) {
            int lin = i * 256 + tid;
            int row = lin >> 3, c4 = lin & 7;
            cpa16(bbase + (uint32_t)(row * GS + c4 * 4) * 4u,
                  Bb + (size_t)row * K + c4 * 4);
        }
        asm volatile("cp.async.commit_group;" ::: "memory");
    };

    const int nc = K / 32;
    load_chunk(0, 0);

    for (int c = 0; c < nc; ++c) {
        const int b = c & 1;
        if (c + 1 < nc) {
            load_chunk(c + 1, b ^ 1);
            asm volatile("cp.async.wait_group 1;" ::: "memory");
        } else {
            asm volatile("cp.async.wait_group 0;" ::: "memory");
        }
        __syncthreads();

        const float* As = sm + b * 2 * TILE_F;
        const float* Bs = As + TILE_F;

#pragma unroll
        for (int ks = 0; ks < 4; ++ks) {
            const int k8 = ks * 8;
            uint32_t af[4][4];
#pragma unroll
            for (int mi = 0; mi < 4; ++mi) {
                const int mr = wm + mi * 16 + lr;
                const int kc = k8 + lc;
                af[mi][0] = f2tf32(As[mr * GS + kc]);
                af[mi][1] = f2tf32(As[(mr + 8) * GS + kc]);
                af[mi][2] = f2tf32(As[mr * GS + kc + 4]);
                af[mi][3] = f2tf32(As[(mr + 8) * GS + kc + 4]);
            }
            uint32_t bf[4][2];
#pragma unroll
            for (int ni = 0; ni < 4; ++ni) {
                const int nr = wn + ni * 8 + lr;
                bf[ni][0] = f2tf32(Bs[nr * GS + k8 + lc]);
                bf[ni][1] = f2tf32(Bs[nr * GS + k8 + lc + 4]);
            }
#pragma unroll
            for (int mi = 0; mi < 4; ++mi)
#pragma unroll
                for (int ni = 0; ni < 4; ++ni)
                    mma_tf32(acc[mi][ni], af[mi], bf[ni]);
        }
        __syncthreads();
    }

    // Epilogue
#pragma unroll
    for (int mi = 0; mi < 4; ++mi) {
        const int r = m0 + wm + mi * 16 + lr;
#pragma unroll
        for (int ni = 0; ni < 4; ++ni) {
            const int cc = n0 + wn + ni * 8 + 2 * lc;
            *(float2*)(C + (size_t)r * N + cc) =
                make_float2(acc[mi][ni][0], acc[mi][ni][1]);
            *(float2*)(C + (size_t)(r + 8) * N + cc) =
                make_float2(acc[mi][ni][2], acc[mi][ni][3]);
        }
    }
}

// ---------------------------------------------------------------------------
// RoPE tables: inv_freq (fp64 exp, once) then cos/sin [T, 64]
// ---------------------------------------------------------------------------
__global__ void rope_init() {
    int j = threadIdx.x;
    g_invf[j] = (float)exp(-(double)(2 * j) * (1.0 / 128.0) * 9.210340371976184);
}
__global__ void rope_table() {
    int t = blockIdx.x, j = threadIdx.x;
    float ang = (float)t * g_invf[j];
    float s, c;
    sincosf(ang, &s, &c);
    g_cos[t * 64 + j] = c;
    g_sin[t * 64 + j] = s;
}

// ---------------------------------------------------------------------------
// RMSNorm + RoPE (+gain). 16 threads per head, 8 floats/thread, table RoPE.
// ---------------------------------------------------------------------------
__global__ void qk_prep2(float* __restrict__ p, const float* __restrict__ gain,
                         int stride)
{
    const int t   = blockIdx.x;
    const int tid = threadIdx.x;
    const int h   = tid >> 4;
    const int s   = tid & 15;

    float* row = p + (size_t)t * stride + h * HD + s * 8;
    float4 a = ((const float4*)row)[0];
    float4 b = ((const float4*)row)[1];
    float v[8] = { a.x, a.y, a.z, a.w, b.x, b.y, b.z, b.w };

    float ss = 0.f;
#pragma unroll
    for (int i = 0; i < 8; ++i) ss += v[i] * v[i];
#pragma unroll
    for (int o = 8; o; o >>= 1) ss += __shfl_xor_sync(0xffffffffu, ss, o);
    float rn = rsqrtf(ss * (1.0f / 128.0f) + 1.1920928955078125e-07f);
    if (gain) rn *= gain[h];

    float pv[8];
#pragma unroll
    for (int i = 0; i < 8; ++i) pv[i] = __shfl_xor_sync(0xffffffffu, v[i], 8);

    const int j0 = (s & 7) * 8;
    float4 c0 = ((const float4*)(g_cos + (size_t)t * 64 + j0))[0];
    float4 c1 = ((const float4*)(g_cos + (size_t)t * 64 + j0))[1];
    float4 s0 = ((const float4*)(g_sin + (size_t)t * 64 + j0))[0];
    float4 s1 = ((const float4*)(g_sin + (size_t)t * 64 + j0))[1];
    float cs[8] = { c0.x, c0.y, c0.z, c0.w, c1.x, c1.y, c1.z, c1.w };
    float sn[8] = { s0.x, s0.y, s0.z, s0.w, s1.x, s1.y, s1.z, s1.w };

    float o[8];
    if (s < 8) {
#pragma unroll
        for (int i = 0; i < 8; ++i) o[i] = (v[i] * cs[i] + pv[i] * sn[i]) * rn;
    } else {
#pragma unroll
        for (int i = 0; i < 8; ++i) o[i] = (v[i] * cs[i] - pv[i] * sn[i]) * rn;
    }
    ((float4*)row)[0] = make_float4(o[0], o[1], o[2], o[3]);
    ((float4*)row)[1] = make_float4(o[4], o[5], o[6], o[7]);
}

// ---------------------------------------------------------------------------
// Flash-style causal attention (fp32) — unchanged from Round 1 (known correct).
// ---------------------------------------------------------------------------
__global__ void __launch_bounds__(256)
attn_kernel(const float* __restrict__ Q, const float* __restrict__ K,
            const float* __restrict__ V, float* __restrict__ O)
{
    extern __shared__ float fsm[];
    float* Qs    = fsm;
    float* Ks    = Qs + 64 * 132;
    float* Vs    = Ks + 64 * 132;
    float* Ps    = Vs + 64 * 128;
    float* rowst = Ps + 64 * 68;

    const int qt  = blockIdx.x;
    const int h   = blockIdx.y;
    const int q0  = qt * 64;
    const int kvh = h >> 2;
    const int tid = threadIdx.x;
    const int w   = tid >> 5;
    const int l   = tid & 31;
    const int rloc = w * 8 + (l >> 2);
    const int grp  = l & 3;
    const int qg   = q0 + rloc;

    for (int i = tid; i < 64 * 32; i += 256) {
        int r = i >> 5, c = i & 31;
        *(float4*)(Qs + r * 132 + c * 4) =
            *(const float4*)(Q + (size_t)(q0 + r) * NDIM + h * HD + c * 4);
    }

    float m_i = -FLT_MAX, l_i = 0.f;
    float o[8][4];
#pragma unroll
    for (int r = 0; r < 8; ++r)
#pragma unroll
        for (int e = 0; e < 4; ++e) o[r][e] = 0.f;

    const float scale = 0.08838834764831845f;

    for (int k0 = 0; k0 <= q0; k0 += 64) {
        __syncthreads();
        for (int i = tid; i < 64 * 32; i += 256) {
            int r = i >> 5, c = i & 31;
            *(float4*)(Ks + r * 132 + c * 4) =
                *(const float4*)(K + (size_t)(k0 + r) * KVDIM + kvh * HD + c * 4);
            *(float4*)(Vs + r * 128 + c * 4) =
                *(const float4*)(V + (size_t)(k0 + r) * KVDIM + kvh * HD + c * 4);
        }
        __syncthreads();

        float s[16];
#pragma unroll
        for (int j = 0; j < 16; ++j) s[j] = 0.f;

        const float* qrow = Qs + rloc * 132;
#pragma unroll 4
        for (int d4 = 0; d4 < 32; ++d4) {
            float4 qv = *(const float4*)(qrow + d4 * 4);
#pragma unroll
            for (int j = 0; j < 16; ++j) {
                float4 kv = *(const float4*)(Ks + (j * 4 + grp) * 132 + d4 * 4);
                s[j] = fmaf(qv.x, kv.x, s[j]);
                s[j] = fmaf(qv.y, kv.y, s[j]);
                s[j] = fmaf(qv.z, kv.z, s[j]);
                s[j] = fmaf(qv.w, kv.w, s[j]);
            }
        }

        float mt = -FLT_MAX;
#pragma unroll
        for (int j = 0; j < 16; ++j) {
            s[j] *= scale;
            if (k0 + j * 4 + grp > qg) s[j] = -FLT_MAX;
            mt = fmaxf(mt, s[j]);
        }
        mt = fmaxf(mt, __shfl_xor_sync(0xffffffffu, mt, 1));
        mt = fmaxf(mt, __shfl_xor_sync(0xffffffffu, mt, 2));
        float m_new = fmaxf(m_i, mt);
        float alpha = expf(m_i - m_new);

        float rowsum = 0.f;
#pragma unroll
        for (int j = 0; j < 16; ++j) {
            float pj = expf(s[j] - m_new);
            Ps[rloc * 68 + j * 4 + grp] = pj;
            rowsum += pj;
        }
        rowsum += __shfl_xor_sync(0xffffffffu, rowsum, 1);
        rowsum += __shfl_xor_sync(0xffffffffu, rowsum, 2);
        l_i = l_i * alpha + rowsum;
        m_i = m_new;
        if (grp == 0) rowst[rloc] = alpha;
        __syncwarp();

#pragma unroll
        for (int r = 0; r < 8; ++r) {
            float a = rowst[w * 8 + r];
#pragma unroll
            for (int e = 0; e < 4; ++e) o[r][e] *= a;
        }
#pragma unroll 2
        for (int c4 = 0; c4 < 16; ++c4) {
            float4 v0 = *(const float4*)(Vs + (c4 * 4 + 0) * 128 + l * 4);
            float4 v1 = *(const float4*)(Vs + (c4 * 4 + 1) * 128 + l * 4);
            float4 v2 = *(const float4*)(Vs + (c4 * 4 + 2) * 128 + l * 4);
            float4 v3 = *(const float4*)(Vs + (c4 * 4 + 3) * 128 + l * 4);
#pragma unroll
            for (int r = 0; r < 8; ++r) {
                float4 pp = *(const float4*)(Ps + (w * 8 + r) * 68 + c4 * 4);
                o[r][0] = fmaf(pp.x, v0.x, o[r][0]); o[r][0] = fmaf(pp.y, v1.x, o[r][0]);
                o[r][0] = fmaf(pp.z, v2.x, o[r][0]); o[r][0] = fmaf(pp.w, v3.x, o[r][0]);
                o[r][1] = fmaf(pp.x, v0.y, o[r][1]); o[r][1] = fmaf(pp.y, v1.y, o[r][1]);
                o[r][1] = fmaf(pp.z, v2.y, o[r][1]); o[r][1] = fmaf(pp.w, v3.y, o[r][1]);
                o[r][2] = fmaf(pp.x, v0.z, o[r][2]); o[r][2] = fmaf(pp.y, v1.z, o[r][2]);
                o[r][2] = fmaf(pp.z, v2.z, o[r][2]); o[r][2] = fmaf(pp.w, v3.z, o[r][2]);
                o[r][3] = fmaf(pp.x, v0.w, o[r][3]); o[r][3] = fmaf(pp.y, v1.w, o[r][3]);
                o[r][3] = fmaf(pp.z, v2.w, o[r][3]); o[r][3] = fmaf(pp.w, v3.w, o[r][3]);
            }
        }
    }

    __syncwarp();
    if (grp == 0) rowst[rloc] = 1.0f / l_i;
    __syncwarp();

#pragma unroll
    for (int r = 0; r < 8; ++r) {
        float inv = rowst[w * 8 + r];
        float4 v = make_float4(o[r][0] * inv, o[r][1] * inv,
                               o[r][2] * inv, o[r][3] * inv);
        *(float4*)(O + (size_t)(q0 + w * 8 + r) * NDIM + h * HD + l * 4) = v;
    }
}

// ---------------------------------------------------------------------------
extern "C" void kernel_launch(void* const* d_in, const int* in_sizes, int n_in,
                              void* d_out, int out_size)
{
    const float* x  = (const float*)d_in[0];
    const float* Wq = (const float*)d_in[1];
    const float* Wk = (const float*)d_in[2];
    const float* Wv = (const float*)d_in[3];
    const float* Wo = (const float*)d_in[4];
    const float* qg = (const float*)d_in[5];
    float* out = (float*)d_out;

    float *q, *k, *v, *att;
    cudaGetSymbolAddress((void**)&q,   g_q);
    cudaGetSymbolAddress((void**)&k,   g_k);
    cudaGetSymbolAddress((void**)&v,   g_v);
    cudaGetSymbolAddress((void**)&att, g_att);

    const int gemm_smem = 4 * TILE_F * 4;   // 73728 B
    cudaFuncSetAttribute(gemm_mma,
                         cudaFuncAttributeMaxDynamicSharedMemorySize, gemm_smem);

    // Projections (mma.sync tf32)
    gemm_mma<<<dim3(NDIM  / 128, T_SEQ / 128), 256, gemm_smem>>>(x, Wq, q, T_SEQ, NDIM,  NDIM);
    gemm_mma<<<dim3(KVDIM / 128, T_SEQ / 128), 256, gemm_smem>>>(x, Wk, k, T_SEQ, KVDIM, NDIM);
    gemm_mma<<<dim3(KVDIM / 128, T_SEQ / 128), 256, gemm_smem>>>(x, Wv, v, T_SEQ, KVDIM, NDIM);

    // RoPE tables + RMSNorm/RoPE/gain
    rope_init<<<1, 64>>>();
    rope_table<<<T_SEQ, 64>>>();
    qk_prep2<<<T_SEQ, NHEADS * 16>>>(q, qg, NDIM);
    qk_prep2<<<T_SEQ, NKV * 16>>>(k, nullptr, KVDIM);

    // Flash attention (fp32)
    const int attn_smem = (64 * 132 * 2 + 64 * 128 + 64 * 68 + 64) * 4;
    cudaFuncSetAttribute(attn_kernel,
                         cudaFuncAttributeMaxDynamicSharedMemorySize, attn_smem);
    attn_kernel<<<dim3(T_SEQ / 64, NHEADS), 256, attn_smem>>>(q, k, v, att);

    // Output projection
    gemm_mma<<<dim3(NDIM / 128, T_SEQ / 128), 256, gemm_smem>>>(att, Wo, out, T_SEQ, NDIM, NDIM);
}